// round 1
// baseline (speedup 1.0000x reference)
#include <cuda_runtime.h>
#include <math.h>

// Problem constants
#define B_  32
#define S_  128
#define T_  64
#define E_  256
#define H_  512      // encoder hidden
#define V_  32000
#define GH  2048     // 4*H encoder gates
#define DH  1024     // decoder hidden (2H)
#define DG  4096     // 4*DH decoder gates
#define TD  63       // T-1 decoder steps

// ---------------- scratch (static device globals; no runtime allocation) ----------------
__device__ float g_pre_f[(size_t)S_ * B_ * GH];    // encoder fwd pregates  [t*B+b][4H]
__device__ float g_pre_b[(size_t)S_ * B_ * GH];    // encoder bwd pregates
__device__ float g_dec_pre[(size_t)TD * B_ * DG];  // decoder pregates
__device__ float g_dec_hs[(size_t)TD * B_ * DH];   // decoder hidden outputs
__device__ float g_enc_h[2][2][B_ * H_];           // [dir][parity][B*H]
__device__ float g_enc_c[2][B_ * H_];              // [dir][B*H]
__device__ float g_dec_h[2][B_ * DH];              // [parity][B*DH]
__device__ float g_dec_c[B_ * DH];
__device__ int   g_enc_rowidx[S_ * B_];
__device__ int   g_dec_rowidx[TD * B_];

// ---------------- prep: zero states, build gather indices, zero out[:,0,:] ----------------
__global__ void prep_k(const int* __restrict__ src, const int* __restrict__ trg,
                       float* __restrict__ out)
{
    long idx = (long)blockIdx.x * blockDim.x + threadIdx.x;
    const long N0 = (long)B_ * V_;
    if (idx < N0) {
        long b = idx / V_, v = idx - b * V_;
        out[(size_t)b * T_ * V_ + v] = 0.f;   // out[:,0,:] = 0
        return;
    }
    idx -= N0;
    if (idx < 2 * B_ * H_) { g_enc_h[idx >> 14][0][idx & 16383] = 0.f; return; }
    idx -= 2 * B_ * H_;
    if (idx < 2 * B_ * H_) { g_enc_c[idx >> 14][idx & 16383] = 0.f; return; }
    idx -= 2 * B_ * H_;
    if (idx < S_ * B_) {
        int t = (int)(idx / B_), b = (int)(idx % B_);
        g_enc_rowidx[idx] = src[b * S_ + t];
        return;
    }
    idx -= S_ * B_;
    if (idx < TD * B_) {
        int t = (int)(idx / B_), b = (int)(idx % B_);
        g_dec_rowidx[idx] = trg[b * T_ + t];
        return;
    }
}

// ---------------- generic SGEMM: C[m][n] = bias[n] + sum_k A[row(m)][k] * W[n][k] ----------
// A: [*, K] row-major, rows gathered via rowidx (or identity if rowidx==nullptr)
// W: [N, K] row-major  (i.e. computes A @ W^T)
// REMAP=1: output row m = t*B+b is written to out row (b*T + t + 1) (final logits layout)
// Tiles: 128x128, BK=16, 256 threads, 8x8 microtile per thread.
template <int REMAP>
__global__ void sgemm_k(const float* __restrict__ A, const float* __restrict__ W,
                        const float* __restrict__ bias, const int* __restrict__ rowidx,
                        float* __restrict__ C, int M, int N, int K)
{
    __shared__ float As[16][128];
    __shared__ float Bs[16][128];
    const int tid = threadIdx.x;
    const int m0 = blockIdx.y * 128;
    const int n0 = blockIdx.x * 128;

    // loader mapping: 128 rows x 2 float4 chunks per thread
    const int lm = tid & 127;
    const int lq = tid >> 7;             // 0 or 1
    int mm = m0 + lm; if (mm >= M) mm = M - 1;
    const int arow = rowidx ? rowidx[mm] : mm;
    const float* aptr = A + (size_t)arow * K;
    const float* bptr = W + (size_t)(n0 + lm) * K;

    const int tx = tid & 15, ty = tid >> 4;
    float acc[8][8];
#pragma unroll
    for (int i = 0; i < 8; i++)
#pragma unroll
        for (int j = 0; j < 8; j++) acc[i][j] = 0.f;

    for (int k0 = 0; k0 < K; k0 += 16) {
        float4 a0 = *(const float4*)(aptr + k0 + 4 * lq);
        float4 a1 = *(const float4*)(aptr + k0 + 4 * lq + 8);
        float4 b0 = *(const float4*)(bptr + k0 + 4 * lq);
        float4 b1 = *(const float4*)(bptr + k0 + 4 * lq + 8);
        __syncthreads();   // previous tile fully consumed
        As[4 * lq + 0][lm] = a0.x; As[4 * lq + 1][lm] = a0.y;
        As[4 * lq + 2][lm] = a0.z; As[4 * lq + 3][lm] = a0.w;
        As[4 * lq + 8][lm] = a1.x; As[4 * lq + 9][lm] = a1.y;
        As[4 * lq + 10][lm] = a1.z; As[4 * lq + 11][lm] = a1.w;
        Bs[4 * lq + 0][lm] = b0.x; Bs[4 * lq + 1][lm] = b0.y;
        Bs[4 * lq + 2][lm] = b0.z; Bs[4 * lq + 3][lm] = b0.w;
        Bs[4 * lq + 8][lm] = b1.x; Bs[4 * lq + 9][lm] = b1.y;
        Bs[4 * lq + 10][lm] = b1.z; Bs[4 * lq + 11][lm] = b1.w;
        __syncthreads();
#pragma unroll
        for (int k = 0; k < 16; k++) {
            float ar[8], br[8];
            *(float4*)&ar[0] = *(const float4*)&As[k][ty * 8];
            *(float4*)&ar[4] = *(const float4*)&As[k][ty * 8 + 4];
            *(float4*)&br[0] = *(const float4*)&Bs[k][tx * 8];
            *(float4*)&br[4] = *(const float4*)&Bs[k][tx * 8 + 4];
#pragma unroll
            for (int i = 0; i < 8; i++)
#pragma unroll
                for (int j = 0; j < 8; j++) acc[i][j] += ar[i] * br[j];
        }
    }

#pragma unroll
    for (int i = 0; i < 8; i++) {
        int m = m0 + ty * 8 + i;
        if (m >= M) break;
        size_t row;
        if (REMAP) { int b = m & (B_ - 1); int t = m >> 5; row = (size_t)(b * T_ + t + 1); }
        else       { row = (size_t)m; }
        float* cp = C + row * (size_t)N + n0 + tx * 8;
        const float* bp = bias + n0 + tx * 8;
#pragma unroll
        for (int j = 0; j < 8; j++) cp[j] = acc[i][j] + bp[j];
    }
}

// ---------------- encoder LSTM step (both directions fused) ----------------
// grid (H/128, B, 2 dirs), block 128. Thread owns one cell j: 4 dot products K=H.
__global__ void enc_step_k(const float* __restrict__ Whh_f,
                           const float* __restrict__ Whh_b, int s)
{
    const int dir = blockIdx.z;
    const int b = blockIdx.y;
    const int j = blockIdx.x * 128 + threadIdx.x;
    const float* Whh = dir ? Whh_b : Whh_f;
    const int t = dir ? (S_ - 1 - s) : s;
    const float* pre = (dir ? g_pre_b : g_pre_f) + ((size_t)t * B_ + b) * GH;
    const float* h_in = g_enc_h[dir][s & 1] + b * H_;
    float* h_out = g_enc_h[dir][(s + 1) & 1] + b * H_;
    float* c = g_enc_c[dir] + b * H_;

    __shared__ float hs[H_];
    for (int k = threadIdx.x; k < H_; k += 128) hs[k] = h_in[k];
    __syncthreads();

    const float4* h4 = (const float4*)hs;
    const float4* wi = (const float4*)(Whh + (size_t)j * H_);
    const float4* wf = (const float4*)(Whh + (size_t)(H_ + j) * H_);
    const float4* wg = (const float4*)(Whh + (size_t)(2 * H_ + j) * H_);
    const float4* wo = (const float4*)(Whh + (size_t)(3 * H_ + j) * H_);
    float ai = pre[j], af = pre[H_ + j], ag = pre[2 * H_ + j], ao = pre[3 * H_ + j];
#pragma unroll 4
    for (int k = 0; k < H_ / 4; k++) {
        float4 h = h4[k];
        float4 a = wi[k]; ai += h.x * a.x + h.y * a.y + h.z * a.z + h.w * a.w;
        float4 f = wf[k]; af += h.x * f.x + h.y * f.y + h.z * f.z + h.w * f.w;
        float4 g = wg[k]; ag += h.x * g.x + h.y * g.y + h.z * g.z + h.w * g.w;
        float4 o = wo[k]; ao += h.x * o.x + h.y * o.y + h.z * o.z + h.w * o.w;
    }
    float iv = 1.f / (1.f + expf(-ai));
    float fv = 1.f / (1.f + expf(-af));
    float gv = tanhf(ag);
    float ov = 1.f / (1.f + expf(-ao));
    float cv = fv * c[j] + iv * gv;
    c[j] = cv;
    h_out[j] = ov * tanhf(cv);
}

// ---------------- decoder init: h0/c0 = concat(fwd, bwd) final states ----------------
__global__ void dec_init_k()
{
    int idx = blockIdx.x * blockDim.x + threadIdx.x;  // 0 .. 65535
    int which = idx >> 15;       // 0: h, 1: c
    int i = idx & 32767;
    int b = i >> 10, j = i & 1023;
    float v;
    if (j < H_) v = which ? g_enc_c[0][b * H_ + j]       : g_enc_h[0][0][b * H_ + j];
    else        v = which ? g_enc_c[1][b * H_ + j - H_]  : g_enc_h[1][0][b * H_ + j - H_];
    if (which) g_dec_c[b * DH + j] = v;
    else       g_dec_h[0][b * DH + j] = v;
}

// ---------------- decoder LSTM step ----------------
// grid (DH/128, B), block 128. Thread owns cell j: 4 dots K=DH.
__global__ void dec_step_k(const float* __restrict__ Whh, int t)
{
    const int b = blockIdx.y;
    const int j = blockIdx.x * 128 + threadIdx.x;
    const float* pre = g_dec_pre + ((size_t)t * B_ + b) * DG;
    const float* h_in = g_dec_h[t & 1] + b * DH;
    float* h_out = g_dec_h[(t + 1) & 1] + b * DH;
    float* c = g_dec_c + b * DH;

    __shared__ float hs[DH];
    for (int k = threadIdx.x; k < DH; k += 128) hs[k] = h_in[k];
    __syncthreads();

    const float4* h4 = (const float4*)hs;
    const float4* wi = (const float4*)(Whh + (size_t)j * DH);
    const float4* wf = (const float4*)(Whh + (size_t)(DH + j) * DH);
    const float4* wg = (const float4*)(Whh + (size_t)(2 * DH + j) * DH);
    const float4* wo = (const float4*)(Whh + (size_t)(3 * DH + j) * DH);
    float ai = pre[j], af = pre[DH + j], ag = pre[2 * DH + j], ao = pre[3 * DH + j];
#pragma unroll 4
    for (int k = 0; k < DH / 4; k++) {
        float4 h = h4[k];
        float4 a = wi[k]; ai += h.x * a.x + h.y * a.y + h.z * a.z + h.w * a.w;
        float4 f = wf[k]; af += h.x * f.x + h.y * f.y + h.z * f.z + h.w * f.w;
        float4 g = wg[k]; ag += h.x * g.x + h.y * g.y + h.z * g.z + h.w * g.w;
        float4 o = wo[k]; ao += h.x * o.x + h.y * o.y + h.z * o.z + h.w * o.w;
    }
    float iv = 1.f / (1.f + expf(-ai));
    float fv = 1.f / (1.f + expf(-af));
    float gv = tanhf(ag);
    float ov = 1.f / (1.f + expf(-ao));
    float cv = fv * c[j] + iv * gv;
    float hv = ov * tanhf(cv);
    c[j] = cv;
    h_out[j] = hv;
    g_dec_hs[((size_t)t * B_ + b) * DH + j] = hv;
}

// ---------------- launch ----------------
extern "C" void kernel_launch(void* const* d_in, const int* in_sizes, int n_in,
                              void* d_out, int out_size)
{
    (void)in_sizes; (void)n_in; (void)out_size;
    const int*   src     = (const int*)d_in[0];
    const int*   trg     = (const int*)d_in[1];
    const float* enc_emb = (const float*)d_in[2];
    const float* dec_emb = (const float*)d_in[3];
    const float* eWih_f  = (const float*)d_in[4];
    const float* eWhh_f  = (const float*)d_in[5];
    const float* eb_f    = (const float*)d_in[6];
    const float* eWih_b  = (const float*)d_in[7];
    const float* eWhh_b  = (const float*)d_in[8];
    const float* eb_b    = (const float*)d_in[9];
    const float* dWih    = (const float*)d_in[10];
    const float* dWhh    = (const float*)d_in[11];
    const float* db      = (const float*)d_in[12];
    const float* fcW     = (const float*)d_in[13];
    const float* fcb     = (const float*)d_in[14];
    float* out = (float*)d_out;

    void *p_pre_f, *p_pre_b, *p_dec_pre, *p_dec_hs, *p_enc_ri, *p_dec_ri;
    cudaGetSymbolAddress(&p_pre_f, g_pre_f);
    cudaGetSymbolAddress(&p_pre_b, g_pre_b);
    cudaGetSymbolAddress(&p_dec_pre, g_dec_pre);
    cudaGetSymbolAddress(&p_dec_hs, g_dec_hs);
    cudaGetSymbolAddress(&p_enc_ri, g_enc_rowidx);
    cudaGetSymbolAddress(&p_dec_ri, g_dec_rowidx);

    // prep: zero out[:,0,:], zero initial states, build gather indices
    long total = (long)B_ * V_ + 2L * B_ * H_ + 2L * B_ * H_ + (long)S_ * B_ + (long)TD * B_;
    prep_k<<<(unsigned)((total + 255) / 256), 256>>>(src, trg, out);

    // pregate GEMMs (gathered embedding rows @ Wih^T + b)
    sgemm_k<0><<<dim3(GH / 128, (S_ * B_) / 128), 256>>>(
        enc_emb, eWih_f, eb_f, (const int*)p_enc_ri, (float*)p_pre_f, S_ * B_, GH, E_);
    sgemm_k<0><<<dim3(GH / 128, (S_ * B_) / 128), 256>>>(
        enc_emb, eWih_b, eb_b, (const int*)p_enc_ri, (float*)p_pre_b, S_ * B_, GH, E_);
    sgemm_k<0><<<dim3(DG / 128, (TD * B_ + 127) / 128), 256>>>(
        dec_emb, dWih, db, (const int*)p_dec_ri, (float*)p_dec_pre, TD * B_, DG, E_);

    // encoder recurrence (fwd + bwd fused per step)
    for (int s = 0; s < S_; s++)
        enc_step_k<<<dim3(H_ / 128, B_, 2), 128>>>(eWhh_f, eWhh_b, s);

    // decoder init + recurrence
    dec_init_k<<<256, 256>>>();
    for (int t = 0; t < TD; t++)
        dec_step_k<<<dim3(DH / 128, B_), 128>>>(dWhh, t);

    // final logits GEMM, remapped into out[b][t+1][:]
    sgemm_k<1><<<dim3(V_ / 128, (TD * B_ + 127) / 128), 256>>>(
        (const float*)p_dec_hs, fcW, fcb, nullptr, out, TD * B_, V_, DH);
}

// round 2
// speedup vs baseline: 2.1511x; 2.1511x over previous
#include <cuda_runtime.h>
#include <math.h>

// Problem constants
#define B_  32
#define S_  128
#define T_  64
#define E_  256
#define H_  512      // encoder hidden
#define V_  32000
#define GH  2048     // 4*H encoder gates
#define DH  1024     // decoder hidden (2H)
#define DG  4096     // 4*DH decoder gates
#define TD  63       // T-1 decoder steps

// ---------------- scratch (static device globals; no runtime allocation) ----------------
// Pregates stored TRANSPOSED: [t][gate_n][b]
__device__ float g_pre_fT[(size_t)S_ * GH * B_];
__device__ float g_pre_bT[(size_t)S_ * GH * B_];
__device__ float g_dec_preT[(size_t)TD * DG * B_];
__device__ float g_dec_hs[(size_t)TD * B_ * DH];     // row-major for final GEMM
// States transposed [cell][b]
__device__ float g_enc_hT[2][2][H_ * B_];            // [dir][parity]
__device__ float g_enc_cT[2][H_ * B_];
__device__ float g_dec_hT[2][DH * B_];
__device__ float g_dec_cT[DH * B_];
__device__ int   g_enc_rowidx[S_ * B_];
__device__ int   g_dec_rowidx[TD * B_];

// ---------------- prep: zero states, build gather indices, zero out[:,0,:] ----------------
__global__ void prep_k(const int* __restrict__ src, const int* __restrict__ trg,
                       float* __restrict__ out)
{
    long idx = (long)blockIdx.x * blockDim.x + threadIdx.x;
    const long N0 = (long)B_ * V_;
    if (idx < N0) {
        long b = idx / V_, v = idx - b * V_;
        out[(size_t)b * T_ * V_ + v] = 0.f;   // out[:,0,:] = 0
        return;
    }
    idx -= N0;
    if (idx < 2 * H_ * B_) { g_enc_hT[idx >> 14][0][idx & 16383] = 0.f; return; }
    idx -= 2 * H_ * B_;
    if (idx < 2 * H_ * B_) { g_enc_cT[idx >> 14][idx & 16383] = 0.f; return; }
    idx -= 2 * H_ * B_;
    if (idx < S_ * B_) {
        int t = (int)(idx / B_), b = (int)(idx % B_);
        g_enc_rowidx[idx] = src[b * S_ + t];
        return;
    }
    idx -= S_ * B_;
    if (idx < TD * B_) {
        int t = (int)(idx / B_), b = (int)(idx % B_);
        g_dec_rowidx[idx] = trg[b * T_ + t];
        return;
    }
}

// ---------------- generic SGEMM: C[m][n] = bias[n] + sum_k A[row(m)][k] * W[n][k] ----------
// OUT_MODE 0: row-major C[m][n]
// OUT_MODE 1: final-logits remap: row m=t*32+b -> out row (b*T + t + 1)
// OUT_MODE 2: pregate transpose: C[((m/32)*N + n)*32 + (m%32)]
template <int OUT_MODE>
__global__ void sgemm_k(const float* __restrict__ A, const float* __restrict__ W,
                        const float* __restrict__ bias, const int* __restrict__ rowidx,
                        float* __restrict__ C, int M, int N, int K)
{
    __shared__ float As[16][128];
    __shared__ float Bs[16][128];
    const int tid = threadIdx.x;
    const int m0 = blockIdx.y * 128;
    const int n0 = blockIdx.x * 128;

    const int lm = tid & 127;
    const int lq = tid >> 7;             // 0 or 1
    int mm = m0 + lm; if (mm >= M) mm = M - 1;
    const int arow = rowidx ? rowidx[mm] : mm;
    const float* aptr = A + (size_t)arow * K;
    const float* bptr = W + (size_t)(n0 + lm) * K;

    const int tx = tid & 15, ty = tid >> 4;
    float acc[8][8];
#pragma unroll
    for (int i = 0; i < 8; i++)
#pragma unroll
        for (int j = 0; j < 8; j++) acc[i][j] = 0.f;

    for (int k0 = 0; k0 < K; k0 += 16) {
        float4 a0 = *(const float4*)(aptr + k0 + 4 * lq);
        float4 a1 = *(const float4*)(aptr + k0 + 4 * lq + 8);
        float4 b0 = *(const float4*)(bptr + k0 + 4 * lq);
        float4 b1 = *(const float4*)(bptr + k0 + 4 * lq + 8);
        __syncthreads();
        As[4 * lq + 0][lm] = a0.x; As[4 * lq + 1][lm] = a0.y;
        As[4 * lq + 2][lm] = a0.z; As[4 * lq + 3][lm] = a0.w;
        As[4 * lq + 8][lm] = a1.x; As[4 * lq + 9][lm] = a1.y;
        As[4 * lq + 10][lm] = a1.z; As[4 * lq + 11][lm] = a1.w;
        Bs[4 * lq + 0][lm] = b0.x; Bs[4 * lq + 1][lm] = b0.y;
        Bs[4 * lq + 2][lm] = b0.z; Bs[4 * lq + 3][lm] = b0.w;
        Bs[4 * lq + 8][lm] = b1.x; Bs[4 * lq + 9][lm] = b1.y;
        Bs[4 * lq + 10][lm] = b1.z; Bs[4 * lq + 11][lm] = b1.w;
        __syncthreads();
#pragma unroll
        for (int k = 0; k < 16; k++) {
            float ar[8], br[8];
            *(float4*)&ar[0] = *(const float4*)&As[k][ty * 8];
            *(float4*)&ar[4] = *(const float4*)&As[k][ty * 8 + 4];
            *(float4*)&br[0] = *(const float4*)&Bs[k][tx * 8];
            *(float4*)&br[4] = *(const float4*)&Bs[k][tx * 8 + 4];
#pragma unroll
            for (int i = 0; i < 8; i++)
#pragma unroll
                for (int j = 0; j < 8; j++) acc[i][j] += ar[i] * br[j];
        }
    }

#pragma unroll
    for (int i = 0; i < 8; i++) {
        int m = m0 + ty * 8 + i;
        if (m >= M) break;
        const float* bp = bias + n0 + tx * 8;
        if (OUT_MODE == 2) {
            int t = m >> 5, b = m & 31;
#pragma unroll
            for (int j = 0; j < 8; j++) {
                int n = n0 + tx * 8 + j;
                C[((size_t)t * N + n) * B_ + b] = acc[i][j] + bp[j];
            }
        } else {
            size_t row;
            if (OUT_MODE == 1) { int b = m & 31; int t = m >> 5; row = (size_t)(b * T_ + t + 1); }
            else               { row = (size_t)m; }
            float* cp = C + row * (size_t)N + n0 + tx * 8;
#pragma unroll
            for (int j = 0; j < 8; j++) cp[j] = acc[i][j] + bp[j];
        }
    }
}

// ---------------- encoder LSTM step: warp = cell, lane = batch ----------------
// grid (H_/8, 2 dirs), 256 threads (8 warps). Whh read ONCE per step per dir.
__global__ void enc_step_k(const float* __restrict__ Whh_f,
                           const float* __restrict__ Whh_b, int s)
{
    extern __shared__ float shT[];   // H_ * 32 floats = 64KB
    const int dir = blockIdx.y;
    const float* Whh = dir ? Whh_b : Whh_f;
    const int t = dir ? (S_ - 1 - s) : s;
    const float* hT_in = g_enc_hT[dir][s & 1];
    float* hT_out = g_enc_hT[dir][(s + 1) & 1];
    float* cT = g_enc_cT[dir];

    // stage full transposed h into smem (coalesced float4)
    {
        const float4* s4 = (const float4*)hT_in;
        float4* d4 = (float4*)shT;
        for (int i = threadIdx.x; i < H_ * B_ / 4; i += 256) d4[i] = s4[i];
    }
    __syncthreads();

    const int w = threadIdx.x >> 5, lane = threadIdx.x & 31;
    const int j = blockIdx.x * 8 + w;

    const float4* wi = (const float4*)(Whh + (size_t)j * H_);
    const float4* wf = (const float4*)(Whh + (size_t)(H_ + j) * H_);
    const float4* wg = (const float4*)(Whh + (size_t)(2 * H_ + j) * H_);
    const float4* wo = (const float4*)(Whh + (size_t)(3 * H_ + j) * H_);

    const float* preT = (dir ? g_pre_bT : g_pre_fT) + (size_t)t * GH * B_;
    float ai = preT[(size_t)(0 * H_ + j) * B_ + lane];
    float af = preT[(size_t)(1 * H_ + j) * B_ + lane];
    float ag = preT[(size_t)(2 * H_ + j) * B_ + lane];
    float ao = preT[(size_t)(3 * H_ + j) * B_ + lane];

#pragma unroll 4
    for (int k4 = 0; k4 < H_ / 4; k4++) {
        float4 a = wi[k4], f = wf[k4], g = wg[k4], o = wo[k4];
        float h0 = shT[(k4 * 4 + 0) * B_ + lane];
        float h1 = shT[(k4 * 4 + 1) * B_ + lane];
        float h2 = shT[(k4 * 4 + 2) * B_ + lane];
        float h3 = shT[(k4 * 4 + 3) * B_ + lane];
        ai += h0 * a.x + h1 * a.y + h2 * a.z + h3 * a.w;
        af += h0 * f.x + h1 * f.y + h2 * f.z + h3 * f.w;
        ag += h0 * g.x + h1 * g.y + h2 * g.z + h3 * g.w;
        ao += h0 * o.x + h1 * o.y + h2 * o.z + h3 * o.w;
    }
    float iv = 1.f / (1.f + expf(-ai));
    float fv = 1.f / (1.f + expf(-af));
    float gv = tanhf(ag);
    float ov = 1.f / (1.f + expf(-ao));
    float cv = fv * cT[(size_t)j * B_ + lane] + iv * gv;
    cT[(size_t)j * B_ + lane] = cv;
    hT_out[(size_t)j * B_ + lane] = ov * tanhf(cv);
}

// ---------------- decoder init: transposed concat of enc final states ----------------
__global__ void dec_init_k()
{
    int idx = blockIdx.x * blockDim.x + threadIdx.x;  // 0 .. 65535
    int which = idx >> 15;       // 0: h, 1: c
    int i = idx & 32767;         // j*32 + b over DH*32
    int j = i >> 5, b = i & 31;
    float v;
    if (j < H_) v = which ? g_enc_cT[0][j * B_ + b] : g_enc_hT[0][0][j * B_ + b];
    else        v = which ? g_enc_cT[1][(j - H_) * B_ + b] : g_enc_hT[1][0][(j - H_) * B_ + b];
    if (which) g_dec_cT[j * B_ + b] = v;
    else       g_dec_hT[0][j * B_ + b] = v;
}

// ---------------- decoder LSTM step: warp = cell, lane = batch ----------------
// grid (DH/8), 256 threads. Needs 128KB dynamic smem.
__global__ void dec_step_k(const float* __restrict__ Whh, int t)
{
    extern __shared__ float shT[];   // DH * 32 floats = 128KB
    const float* hT_in = g_dec_hT[t & 1];
    float* hT_out = g_dec_hT[(t + 1) & 1];

    {
        const float4* s4 = (const float4*)hT_in;
        float4* d4 = (float4*)shT;
        for (int i = threadIdx.x; i < DH * B_ / 4; i += 256) d4[i] = s4[i];
    }
    __syncthreads();

    const int w = threadIdx.x >> 5, lane = threadIdx.x & 31;
    const int j = blockIdx.x * 8 + w;

    const float4* wi = (const float4*)(Whh + (size_t)j * DH);
    const float4* wf = (const float4*)(Whh + (size_t)(DH + j) * DH);
    const float4* wg = (const float4*)(Whh + (size_t)(2 * DH + j) * DH);
    const float4* wo = (const float4*)(Whh + (size_t)(3 * DH + j) * DH);

    const float* preT = g_dec_preT + (size_t)t * DG * B_;
    float ai = preT[(size_t)(0 * DH + j) * B_ + lane];
    float af = preT[(size_t)(1 * DH + j) * B_ + lane];
    float ag = preT[(size_t)(2 * DH + j) * B_ + lane];
    float ao = preT[(size_t)(3 * DH + j) * B_ + lane];

#pragma unroll 4
    for (int k4 = 0; k4 < DH / 4; k4++) {
        float4 a = wi[k4], f = wf[k4], g = wg[k4], o = wo[k4];
        float h0 = shT[(k4 * 4 + 0) * B_ + lane];
        float h1 = shT[(k4 * 4 + 1) * B_ + lane];
        float h2 = shT[(k4 * 4 + 2) * B_ + lane];
        float h3 = shT[(k4 * 4 + 3) * B_ + lane];
        ai += h0 * a.x + h1 * a.y + h2 * a.z + h3 * a.w;
        af += h0 * f.x + h1 * f.y + h2 * f.z + h3 * f.w;
        ag += h0 * g.x + h1 * g.y + h2 * g.z + h3 * g.w;
        ao += h0 * o.x + h1 * o.y + h2 * o.z + h3 * o.w;
    }
    float iv = 1.f / (1.f + expf(-ai));
    float fv = 1.f / (1.f + expf(-af));
    float gv = tanhf(ag);
    float ov = 1.f / (1.f + expf(-ao));
    float cv = fv * g_dec_cT[(size_t)j * B_ + lane] + iv * gv;
    float hv = ov * tanhf(cv);
    g_dec_cT[(size_t)j * B_ + lane] = cv;
    hT_out[(size_t)j * B_ + lane] = hv;
    // row-major copy for final GEMM (strided scalar store, tiny volume)
    g_dec_hs[((size_t)t * B_ + lane) * DH + j] = hv;
}

// ---------------- launch ----------------
extern "C" void kernel_launch(void* const* d_in, const int* in_sizes, int n_in,
                              void* d_out, int out_size)
{
    (void)in_sizes; (void)n_in; (void)out_size;
    const int*   src     = (const int*)d_in[0];
    const int*   trg     = (const int*)d_in[1];
    const float* enc_emb = (const float*)d_in[2];
    const float* dec_emb = (const float*)d_in[3];
    const float* eWih_f  = (const float*)d_in[4];
    const float* eWhh_f  = (const float*)d_in[5];
    const float* eb_f    = (const float*)d_in[6];
    const float* eWih_b  = (const float*)d_in[7];
    const float* eWhh_b  = (const float*)d_in[8];
    const float* eb_b    = (const float*)d_in[9];
    const float* dWih    = (const float*)d_in[10];
    const float* dWhh    = (const float*)d_in[11];
    const float* db      = (const float*)d_in[12];
    const float* fcW     = (const float*)d_in[13];
    const float* fcb     = (const float*)d_in[14];
    float* out = (float*)d_out;

    static int configured = 0;
    if (!configured) {
        cudaFuncSetAttribute(enc_step_k, cudaFuncAttributeMaxDynamicSharedMemorySize,
                             H_ * B_ * 4);
        cudaFuncSetAttribute(dec_step_k, cudaFuncAttributeMaxDynamicSharedMemorySize,
                             DH * B_ * 4);
        configured = 1;
    }

    void *p_pre_fT, *p_pre_bT, *p_dec_preT, *p_dec_hs, *p_enc_ri, *p_dec_ri;
    cudaGetSymbolAddress(&p_pre_fT, g_pre_fT);
    cudaGetSymbolAddress(&p_pre_bT, g_pre_bT);
    cudaGetSymbolAddress(&p_dec_preT, g_dec_preT);
    cudaGetSymbolAddress(&p_dec_hs, g_dec_hs);
    cudaGetSymbolAddress(&p_enc_ri, g_enc_rowidx);
    cudaGetSymbolAddress(&p_dec_ri, g_dec_rowidx);

    long total = (long)B_ * V_ + 2L * H_ * B_ + 2L * H_ * B_ + (long)S_ * B_ + (long)TD * B_;
    prep_k<<<(unsigned)((total + 255) / 256), 256>>>(src, trg, out);

    // pregate GEMMs -> transposed [t][gate][b]
    sgemm_k<2><<<dim3(GH / 128, (S_ * B_) / 128), 256>>>(
        enc_emb, eWih_f, eb_f, (const int*)p_enc_ri, (float*)p_pre_fT, S_ * B_, GH, E_);
    sgemm_k<2><<<dim3(GH / 128, (S_ * B_) / 128), 256>>>(
        enc_emb, eWih_b, eb_b, (const int*)p_enc_ri, (float*)p_pre_bT, S_ * B_, GH, E_);
    sgemm_k<2><<<dim3(DG / 128, (TD * B_ + 127) / 128), 256>>>(
        dec_emb, dWih, db, (const int*)p_dec_ri, (float*)p_dec_preT, TD * B_, DG, E_);

    // encoder recurrence (fwd + bwd fused per step)
    for (int s = 0; s < S_; s++)
        enc_step_k<<<dim3(H_ / 8, 2), 256, H_ * B_ * 4>>>(eWhh_f, eWhh_b, s);

    // decoder init + recurrence
    dec_init_k<<<256, 256>>>();
    for (int t = 0; t < TD; t++)
        dec_step_k<<<DH / 8, 256, DH * B_ * 4>>>(dWhh, t);

    // final logits GEMM, remapped into out[b][t+1][:]
    sgemm_k<1><<<dim3(V_ / 128, (TD * B_ + 127) / 128), 256>>>(
        (const float*)p_dec_hs, fcW, fcb, nullptr, out, TD * B_, V_, DH);
}